// round 15
// baseline (speedup 1.0000x reference)
#include <cuda_runtime.h>
#include <cuda_bf16.h>
#include <math.h>

#define SEQ   2048
#define BATCH 2
#define NHEADS 16
#define HDIM  64
#define MDIM  1024

#define MASKED (-2e30f)
#define MINIT  (-1e30f)

// ---------------- scratch (device globals; no allocations allowed) ----------
__device__ __align__(16) unsigned g_Xh[4096*512],  g_Xl[4096*512];    // X bf16 hi/lo
__device__ __align__(16) unsigned g_Wqh[3072*512], g_Wql[3072*512];   // qkv_w
__device__ __align__(16) unsigned g_Pwh[1024*512], g_Pwl[1024*512];   // proj_w
__device__ __align__(16) unsigned g_qh[65536*32],  g_ql[65536*32];    // (b,h,n) rows of 64 d
__device__ __align__(16) unsigned g_kh[65536*32],  g_kl[65536*32];
__device__ __align__(16) unsigned g_vh[65536*32],  g_vl[65536*32];
__device__ __align__(16) unsigned g_aoh[4096*512], g_aol[4096*512];   // attn out bf16 hi/lo
__device__ unsigned g_mb[4096*64];                                    // mask bits
__device__ int g_mask_kind;

// ---------------- helpers ----------------------------------------------------
__device__ __forceinline__ void cvt_pack(float x0, float x1, unsigned &h, unsigned &l)
{
    __nv_bfloat16 h0 = __float2bfloat16_rn(x0);
    __nv_bfloat16 h1 = __float2bfloat16_rn(x1);
    __nv_bfloat16 l0 = __float2bfloat16_rn(x0 - __bfloat162float(h0));
    __nv_bfloat16 l1 = __float2bfloat16_rn(x1 - __bfloat162float(h1));
    __nv_bfloat162 hp; hp.x = h0; hp.y = h1;
    __nv_bfloat162 lp; lp.x = l0; lp.y = l1;
    h = *reinterpret_cast<unsigned*>(&hp);
    l = *reinterpret_cast<unsigned*>(&lp);
}

__device__ __forceinline__ void mma_bf16(float* c, const unsigned* a, const unsigned* b)
{
    asm volatile(
        "mma.sync.aligned.m16n8k16.row.col.f32.bf16.bf16.f32 "
        "{%0,%1,%2,%3},{%4,%5,%6,%7},{%8,%9},{%0,%1,%2,%3};"
        : "+f"(c[0]), "+f"(c[1]), "+f"(c[2]), "+f"(c[3])
        : "r"(a[0]), "r"(a[1]), "r"(a[2]), "r"(a[3]), "r"(b[0]), "r"(b[1]));
}

__device__ __forceinline__ void cp16(unsigned dst, const void* src)
{
    asm volatile("cp.async.cg.shared.global [%0], [%1], 16;" :: "r"(dst), "l"(src));
}
__device__ __forceinline__ void cp_commit() { asm volatile("cp.async.commit_group;"); }
template<int N> __device__ __forceinline__ void cp_wait()
{ asm volatile("cp.async.wait_group %0;" :: "n"(N)); }

__device__ __forceinline__ void ldsm4(unsigned a, unsigned &r0, unsigned &r1,
                                      unsigned &r2, unsigned &r3)
{
    asm volatile("ldmatrix.sync.aligned.m8n8.x4.shared.b16 {%0,%1,%2,%3}, [%4];"
        : "=r"(r0), "=r"(r1), "=r"(r2), "=r"(r3) : "r"(a));
}
__device__ __forceinline__ void ldsm4t(unsigned a, unsigned &r0, unsigned &r1,
                                       unsigned &r2, unsigned &r3)
{
    asm volatile("ldmatrix.sync.aligned.m8n8.x4.trans.shared.b16 {%0,%1,%2,%3}, [%4];"
        : "=r"(r0), "=r"(r1), "=r"(r2), "=r"(r3) : "r"(a));
}

// ---------------- prep kernels ----------------------------------------------
__global__ void probe_mask_kernel(const unsigned int* __restrict__ m)
{
    __shared__ int s_ni, s_nf;
    if (threadIdx.x == 0) { s_ni = 0; s_nf = 0; }
    __syncthreads();
    int ni = 0, nf = 0;
    for (int i = threadIdx.x; i < 4096; i += 256) {
        unsigned w = m[i];
        if (w > 1u) ni = 1;
        if (w != 0u && w != 0x3F800000u) nf = 1;
    }
    if (ni) atomicOr(&s_ni, 1);
    if (nf) atomicOr(&s_nf, 1);
    __syncthreads();
    if (threadIdx.x == 0)
        g_mask_kind = (s_ni == 0) ? 0 : (s_nf == 0) ? 2 : 1;
}

__global__ void mask_pack_kernel(const void* __restrict__ maskp)
{
    int w = blockIdx.x*256 + threadIdx.x;
    int word = w & 63, row = w >> 6;
    size_t off = (size_t)row*SEQ + word*32;
    unsigned bits = 0;
    if (g_mask_kind == 1) {
        const uchar4* p = (const uchar4*)((const unsigned char*)maskp + off);
#pragma unroll
        for (int i = 0; i < 8; i++) {
            uchar4 u4 = p[i];
            bits |= (u4.x ? 1u : 0u) << (i*4);
            bits |= (u4.y ? 1u : 0u) << (i*4+1);
            bits |= (u4.z ? 1u : 0u) << (i*4+2);
            bits |= (u4.w ? 1u : 0u) << (i*4+3);
        }
    } else {
        const uint4* p = (const uint4*)((const unsigned*)maskp + off);
#pragma unroll
        for (int i = 0; i < 8; i++) {
            uint4 u4 = p[i];
            bits |= (u4.x ? 1u : 0u) << (i*4);
            bits |= (u4.y ? 1u : 0u) << (i*4+1);
            bits |= (u4.z ? 1u : 0u) << (i*4+2);
            bits |= (u4.w ? 1u : 0u) << (i*4+3);
        }
    }
    g_mb[w] = bits;
}

#define NW_X   (4096*512)
#define NW_WQ  (3072*512)
#define NW_PW  (1024*512)
__global__ void convert_all_kernel(const float* __restrict__ x,
                                   const float* __restrict__ qkv_w,
                                   const float* __restrict__ proj_w)
{
    int i = blockIdx.x*256 + threadIdx.x;
    const float* src; unsigned *H, *L; int idx;
    if (i < NW_X)                 { src = x;      H = g_Xh;  L = g_Xl;  idx = i; }
    else if (i < NW_X + NW_WQ)    { src = qkv_w;  H = g_Wqh; L = g_Wql; idx = i - NW_X; }
    else                          { src = proj_w; H = g_Pwh; L = g_Pwl; idx = i - NW_X - NW_WQ; }
    float2 v = ((const float2*)src)[idx];
    unsigned h, l;
    cvt_pack(v.x, v.y, h, l);
    H[idx] = h; L[idx] = l;
}

// ---------------- shared GEMM mainloop (BK=64, 2-stage, halved barriers) ----
// stage = two 32-k sub-blocks of 24KB each = 48KB; 2 buffers = 96KB dyn smem.
// sub-block layout identical to R7: A 128x128B (chunks 0-3 hi, 4-7 lo) + B 64x128B.
__device__ __forceinline__ void gemm_mainloop(
    const unsigned* __restrict__ Agh, const unsigned* __restrict__ Agl,
    const unsigned* __restrict__ Bgh, const unsigned* __restrict__ Bgl,
    unsigned* sm, int m0, int n0, float acc[2][4][4])
{
    const int tid = threadIdx.x;
    const int lane = tid & 31, warp = tid >> 5;
    const int warp_m = warp >> 1, warp_n = warp & 1;
    unsigned smb = (unsigned)__cvta_generic_to_shared(sm);

    // copy 32-k block `kb32` into sub-block slot at `base`
    auto stage_half = [&](int kb32, unsigned base) {
#pragma unroll
        for (int u = 0; u < 4; u++) {
            int ci = tid + u*256;
            int row = ci >> 3, cc = ci & 7, hl = cc >> 2, c = cc & 3;
            const unsigned* src = (hl ? Agl : Agh) + (size_t)(m0+row)*512 + kb32*16 + c*4;
            cp16(base + row*128 + ((cc ^ (row&7))<<4), src);
        }
        unsigned bb = base + 16384;
#pragma unroll
        for (int u = 0; u < 2; u++) {
            int ci = tid + u*256;
            int row = ci >> 3, cc = ci & 7, hl = cc >> 2, c = cc & 3;
            const unsigned* src = (hl ? Bgl : Bgh) + (size_t)(n0+row)*512 + kb32*16 + c*4;
            cp16(bb + row*128 + ((cc ^ (row&7))<<4), src);
        }
    };
    auto stage = [&](int it, int buf) {
        unsigned base = smb + buf*49152;
        stage_half(2*it,     base);
        stage_half(2*it + 1, base + 24576);
    };

    stage(0, 0); cp_commit();

    for (int it = 0; it < 16; it++) {
        cp_wait<0>();
        __syncthreads();
        if (it + 1 < 16) { stage(it+1, (it+1)&1); cp_commit(); }

#pragma unroll
        for (int half = 0; half < 2; half++) {
            unsigned ab = smb + (it&1)*49152 + half*24576;
            unsigned bb = ab + 16384;
#pragma unroll
            for (int ks = 0; ks < 2; ks++) {
                unsigned ah[2][4], al[2][4], bh[4][2], bl[4][2];
#pragma unroll
                for (int mt = 0; mt < 2; mt++) {
                    int row = warp_m*32 + mt*16 + (lane & 15);
                    int ch = 2*ks + (lane >> 4);
                    ldsm4(ab + row*128 + ((ch       ^ (row&7))<<4),
                          ah[mt][0], ah[mt][1], ah[mt][2], ah[mt][3]);
                    ldsm4(ab + row*128 + (((ch + 4) ^ (row&7))<<4),
                          al[mt][0], al[mt][1], al[mt][2], al[mt][3]);
                }
#pragma unroll
                for (int ntp = 0; ntp < 2; ntp++) {
                    int row = warp_n*32 + ntp*16 + (lane & 7) + ((lane & 16) >> 1);
                    int ch = 2*ks + ((lane >> 3) & 1);
                    unsigned r0, r1, r2, r3;
                    ldsm4(bb + row*128 + ((ch ^ (row&7))<<4), r0, r1, r2, r3);
                    bh[2*ntp][0] = r0; bh[2*ntp][1] = r1;
                    bh[2*ntp+1][0] = r2; bh[2*ntp+1][1] = r3;
                    ldsm4(bb + row*128 + (((ch + 4) ^ (row&7))<<4), r0, r1, r2, r3);
                    bl[2*ntp][0] = r0; bl[2*ntp][1] = r1;
                    bl[2*ntp+1][0] = r2; bl[2*ntp+1][1] = r3;
                }
#pragma unroll
                for (int mt = 0; mt < 2; mt++)
#pragma unroll
                    for (int nt = 0; nt < 4; nt++) {
                        mma_bf16(acc[mt][nt], ah[mt], bh[nt]);
                        mma_bf16(acc[mt][nt], ah[mt], bl[nt]);
                        mma_bf16(acc[mt][nt], al[mt], bh[nt]);
                    }
            }
        }
    }
}

// packed bf16 hi/lo pair store for LN/V epilogue
__device__ __forceinline__ void pack_store_pair(
    unsigned* __restrict__ H, unsigned* __restrict__ L,
    size_t wbase, int lane, float y1, float y2)
{
    float y1o = __shfl_xor_sync(0xffffffffu, y1, 1);
    float y2o = __shfl_xor_sync(0xffffffffu, y2, 1);
    if (!(lane & 1)) {
        unsigned h1, l1, h2, l2;
        cvt_pack(y1, y1o, h1, l1);
        cvt_pack(y2, y2o, h2, l2);
        H[wbase + (lane>>1)]      = h1;
        H[wbase + 16 + (lane>>1)] = h2;
        L[wbase + (lane>>1)]      = l1;
        L[wbase + 16 + (lane>>1)] = l2;
    }
}

// ---------------- kernel 1: QKV GEMM + fused layernorm -> packed bf16 -------
// q is additionally scaled by 0.125 * log2(e) so flash can use exp2.
#define QSCALE 0.18033688011112042f
__global__ __launch_bounds__(256, 2) void qkv_gemm_ln_kernel(
    const float* __restrict__ qw, const float* __restrict__ qb,
    const float* __restrict__ kw, const float* __restrict__ kb)
{
    extern __shared__ __align__(16) unsigned gsm[];
    const int tid = threadIdx.x;
    const int m0 = blockIdx.y * 128, n0 = blockIdx.x * 64;
    const int warp = tid >> 5, lane = tid & 31;
    const int warp_m = warp >> 1, warp_n = warp & 1;
    const int group = lane >> 2, tg = lane & 3;

    float acc[2][4][4];
#pragma unroll
    for (int mt = 0; mt < 2; mt++)
#pragma unroll
        for (int nt = 0; nt < 4; nt++)
#pragma unroll
            for (int j = 0; j < 4; j++) acc[mt][nt][j] = 0.f;

    gemm_mainloop(g_Xh, g_Xl, g_Wqh, g_Wql, gsm, m0, n0, acc);

    const int s = n0 >> 10;
    const int h = (n0 & 1023) >> 6;
    float* et = (float*)gsm;

    for (int rh = 0; rh < 2; rh++) {
        __syncthreads();
        if ((warp_m >> 1) == rh) {
#pragma unroll
            for (int mt = 0; mt < 2; mt++)
#pragma unroll
                for (int nt = 0; nt < 4; nt++) {
                    int r0 = warp_m*32 + mt*16 + group - rh*64;
                    int col = warp_n*32 + nt*8 + 2*tg;
                    *(float2*)&et[r0*66 + col] =
                        make_float2(acc[mt][nt][0], acc[mt][nt][1]);
                    *(float2*)&et[(r0+8)*66 + col] =
                        make_float2(acc[mt][nt][2], acc[mt][nt][3]);
                }
        }
        __syncthreads();
#pragma unroll
        for (int rr = 0; rr < 8; rr++) {
            int r  = warp*8 + rr;
            int gm = m0 + rh*64 + r;
            int bb = gm >> 11, n = gm & 2047;
            float v1 = et[r*66 + lane];
            float v2 = et[r*66 + lane + 32];
            size_t wbase = (((size_t)(bb*NHEADS + h))*SEQ + n)*32;
            if (s == 2) {
                pack_store_pair(g_vh, g_vl, wbase, lane, v1, v2);
            } else {
                float sum = v1 + v2, sq = v1*v1 + v2*v2;
#pragma unroll
                for (int o = 16; o; o >>= 1) {
                    sum += __shfl_xor_sync(0xffffffffu, sum, o);
                    sq  += __shfl_xor_sync(0xffffffffu, sq,  o);
                }
                float mean = sum * (1.f/64.f);
                float var  = sq  * (1.f/64.f) - mean*mean;
                float rstd = rsqrtf(var + 1e-5f);
                if (s == 0) {
                    float y1 = ((v1-mean)*rstd*qw[lane]    + qb[lane])    * QSCALE;
                    float y2 = ((v2-mean)*rstd*qw[lane+32] + qb[lane+32]) * QSCALE;
                    pack_store_pair(g_qh, g_ql, wbase, lane, y1, y2);
                } else {
                    float y1 = (v1-mean)*rstd*kw[lane]    + kb[lane];
                    float y2 = (v2-mean)*rstd*kw[lane+32] + kb[lane+32];
                    pack_store_pair(g_kh, g_kl, wbase, lane, y1, y2);
                }
            }
        }
    }
}

// ---------------- kernel 3: output projection + bias ------------------------
__global__ __launch_bounds__(256, 2) void proj_gemm_kernel(
    const float* __restrict__ bias, float* __restrict__ out)
{
    extern __shared__ __align__(16) unsigned gsm[];
    const int tid = threadIdx.x;
    const int m0 = blockIdx.y * 128, n0 = blockIdx.x * 64;
    const int warp = tid >> 5, lane = tid & 31;
    const int warp_m = warp >> 1, warp_n = warp & 1;
    const int group = lane >> 2, tg = lane & 3;

    float acc[2][4][4];
#pragma unroll
    for (int mt = 0; mt < 2; mt++)
#pragma unroll
        for (int nt = 0; nt < 4; nt++)
#pragma unroll
            for (int j = 0; j < 4; j++) acc[mt][nt][j] = 0.f;

    gemm_mainloop(g_aoh, g_aol, g_Pwh, g_Pwl, gsm, m0, n0, acc);

#pragma unroll
    for (int nt = 0; nt < 4; nt++) {
        int col = n0 + warp_n*32 + nt*8 + 2*tg;
        float b0 = bias[col], b1 = bias[col+1];
#pragma unroll
        for (int mt = 0; mt < 2; mt++) {
            int row = m0 + warp_m*32 + mt*16 + group;
            *(float2*)(out + (size_t)row*MDIM + col) =
                make_float2(acc[mt][nt][0] + b0, acc[mt][nt][1] + b1);
            *(float2*)(out + (size_t)(row+8)*MDIM + col) =
                make_float2(acc[mt][nt][2] + b0, acc[mt][nt][3] + b1);
        }
    }
}

// ---------------- kernel 2: flash attention (R13 best: 2 CTAs/SM) -----------
__global__ __launch_bounds__(256, 2) void flash_attn_mma_kernel()
{
    extern __shared__ __align__(16) unsigned fsm[];
    const int tid = threadIdx.x;
    const int warp = tid >> 5, lane = tid & 31;
    const int group = lane >> 2, tg = lane & 3;
    const int q0 = blockIdx.x * 128, h = blockIdx.y, b = blockIdx.z;
    const int bhrow = (b*NHEADS + h)*SEQ;
    unsigned smb = (unsigned)__cvta_generic_to_shared(fsm);
    const unsigned kvb0 = smb + 32768;        // KV buffers base

    // ---- stage Q tile (persistent: hi at +0, lo at +16KB) ----
#pragma unroll
    for (int u = 0; u < 8; u++) {
        int ci = tid + u*256;
        int hl = ci >> 10, wi = ci & 1023;
        int row = wi >> 3, c = wi & 7;
        const unsigned* src = (hl ? g_ql : g_qh) + (size_t)(bhrow + q0 + row)*32 + c*4;
        cp16(smb + hl*16384 + row*128 + ((c ^ (row&7))<<4), src);
    }
    cp_commit();

    auto stageKV = [&](int kt, int buf) {
        unsigned base = kvb0 + buf*32768;
#pragma unroll
        for (int u = 0; u < 8; u++) {
            int ci = tid + u*256;
            int arr = ci >> 9, wi = ci & 511;
            int row = wi >> 3, c = wi & 7;
            const unsigned* sa;
            if (arr == 0) sa = g_kh; else if (arr == 1) sa = g_kl;
            else if (arr == 2) sa = g_vh; else sa = g_vl;
            const unsigned* src = sa + (size_t)(bhrow + kt*64 + row)*32 + c*4;
            cp16(base + arr*8192 + row*128 + ((c ^ (row&7))<<4), src);
        }
    };

    stageKV(0, 0); cp_commit();

    float m0r = MINIT, m1r = MINIT, l0r = 0.f, l1r = 0.f;
    float o[8][4];
#pragma unroll
    for (int nt = 0; nt < 8; nt++)
#pragma unroll
        for (int j = 0; j < 4; j++) o[nt][j] = 0.f;

    const int lr = warp*16 + group;
    const unsigned* mb0 = g_mb + (size_t)(b*SEQ + q0 + lr)*64;
    const unsigned* mb1 = g_mb + (size_t)(b*SEQ + q0 + lr + 8)*64;

    for (int kt = 0; kt < SEQ/64; kt++) {
        unsigned w0lo = mb0[kt*2], w0hi = mb0[kt*2+1];
        unsigned w1lo = mb1[kt*2], w1hi = mb1[kt*2+1];
        cp_wait<0>();
        __syncthreads();
        if (kt + 1 < SEQ/64) { stageKV(kt+1, (kt+1)&1); cp_commit(); }

        unsigned kb = kvb0 + (kt&1)*32768;

        // ---- S = Q K^T (bf16x3); Q frags re-loaded from smem per ks ----
        float s[8][4];
#pragma unroll
        for (int nt = 0; nt < 8; nt++)
#pragma unroll
            for (int j = 0; j < 4; j++) s[nt][j] = 0.f;
#pragma unroll
        for (int ks = 0; ks < 4; ks++) {
            unsigned qhf[4], qlf[4];
            {
                int row = warp*16 + (lane & 15);
                int ch = 2*ks + (lane >> 4);
                unsigned a = row*128 + ((ch ^ (row&7))<<4);
                ldsm4(smb + a,         qhf[0], qhf[1], qhf[2], qhf[3]);
                ldsm4(smb + 16384 + a, qlf[0], qlf[1], qlf[2], qlf[3]);
            }
#pragma unroll
            for (int ntp = 0; ntp < 4; ntp++) {
                int row = ntp*16 + (lane & 7) + ((lane & 16) >> 1);
                int ch = 2*ks + ((lane >> 3) & 1);
                unsigned a = kb + row*128 + ((ch ^ (row&7))<<4);
                unsigned bh0[2], bh1[2], bl0[2], bl1[2];
                ldsm4(a,        bh0[0], bh0[1], bh1[0], bh1[1]);
                ldsm4(a + 8192, bl0[0], bl0[1], bl1[0], bl1[1]);
                mma_bf16(s[2*ntp],   qhf, bh0);
                mma_bf16(s[2*ntp],   qhf, bl0);
                mma_bf16(s[2*ntp],   qlf, bh0);
                mma_bf16(s[2*ntp+1], qhf, bh1);
                mma_bf16(s[2*ntp+1], qhf, bl1);
                mma_bf16(s[2*ntp+1], qlf, bh1);
            }
        }

        // ---- mask + online softmax (base-2) ----
        float rm0 = MINIT, rm1 = MINIT;
#pragma unroll
        for (int nt = 0; nt < 8; nt++) {
            int kidx = nt*8 + 2*tg;
            unsigned wr0 = (nt < 4) ? w0lo : w0hi;
            unsigned wr1 = (nt < 4) ? w1lo : w1hi;
            int sh = kidx & 31;
            if ((wr0 >> sh) & 1)     s[nt][0] = MASKED;
            if ((wr0 >> (sh+1)) & 1) s[nt][1] = MASKED;
            if ((wr1 >> sh) & 1)     s[nt][2] = MASKED;
            if ((wr1 >> (sh+1)) & 1) s[nt][3] = MASKED;
            rm0 = fmaxf(rm0, fmaxf(s[nt][0], s[nt][1]));
            rm1 = fmaxf(rm1, fmaxf(s[nt][2], s[nt][3]));
        }
        rm0 = fmaxf(rm0, __shfl_xor_sync(0xffffffffu, rm0, 1));
        rm0 = fmaxf(rm0, __shfl_xor_sync(0xffffffffu, rm0, 2));
        rm1 = fmaxf(rm1, __shfl_xor_sync(0xffffffffu, rm1, 1));
        rm1 = fmaxf(rm1, __shfl_xor_sync(0xffffffffu, rm1, 2));
        float mn0 = fmaxf(m0r, rm0), mn1 = fmaxf(m1r, rm1);
        float c0 = exp2f(m0r - mn0), c1 = exp2f(m1r - mn1);
        m0r = mn0; m1r = mn1;

        float ls0 = 0.f, ls1 = 0.f;
#pragma unroll
        for (int nt = 0; nt < 8; nt++) {
            s[nt][0] = exp2f(s[nt][0] - mn0);
            s[nt][1] = exp2f(s[nt][1] - mn0);
            s[nt][2] = exp2f(s[nt][2] - mn1);
            s[nt][3] = exp2f(s[nt][3] - mn1);
            ls0 += s[nt][0] + s[nt][1];
            ls1 += s[nt][2] + s[nt][3];
        }
        ls0 += __shfl_xor_sync(0xffffffffu, ls0, 1);
        ls0 += __shfl_xor_sync(0xffffffffu, ls0, 2);
        ls1 += __shfl_xor_sync(0xffffffffu, ls1, 1);
        ls1 += __shfl_xor_sync(0xffffffffu, ls1, 2);
        l0r = l0r*c0 + ls0;
        l1r = l1r*c1 + ls1;
#pragma unroll
        for (int nt = 0; nt < 8; nt++) {
            o[nt][0] *= c0; o[nt][1] *= c0;
            o[nt][2] *= c1; o[nt][3] *= c1;
        }

        // ---- P fragments from S accumulators ----
        unsigned ph[4][4], pl[4][4];
#pragma unroll
        for (int j = 0; j < 4; j++) {
            cvt_pack(s[2*j][0],   s[2*j][1],   ph[j][0], pl[j][0]);
            cvt_pack(s[2*j][2],   s[2*j][3],   ph[j][1], pl[j][1]);
            cvt_pack(s[2*j+1][0], s[2*j+1][1], ph[j][2], pl[j][2]);
            cvt_pack(s[2*j+1][2], s[2*j+1][3], ph[j][3], pl[j][3]);
        }

        // ---- O += P V (V via ldmatrix.trans) ----
        unsigned vb = kb + 16384;
#pragma unroll
        for (int nt = 0; nt < 8; nt++) {
#pragma unroll
            for (int jp = 0; jp < 2; jp++) {
                int row = jp*32 + lane;
                unsigned a = vb + row*128 + ((nt ^ (row&7))<<4);
                unsigned vh0[2], vh1[2], vl0[2], vl1[2];
                ldsm4t(a,        vh0[0], vh0[1], vh1[0], vh1[1]);
                ldsm4t(a + 8192, vl0[0], vl0[1], vl1[0], vl1[1]);
                mma_bf16(o[nt], ph[2*jp],   vh0);
                mma_bf16(o[nt], ph[2*jp],   vl0);
                mma_bf16(o[nt], pl[2*jp],   vh0);
                mma_bf16(o[nt], ph[2*jp+1], vh1);
                mma_bf16(o[nt], ph[2*jp+1], vl1);
                mma_bf16(o[nt], pl[2*jp+1], vh1);
            }
        }
    }

    // ---- finalize: pack to bf16 hi/lo ao ----
    const int row0 = q0 + warp*16 + group;
    float inv0 = 1.f / l0r, inv1 = 1.f / l1r;
#pragma unroll
    for (int nt = 0; nt < 8; nt++) {
        int widx = h*32 + nt*4 + tg;
        unsigned hh, ll;
        cvt_pack(o[nt][0]*inv0, o[nt][1]*inv0, hh, ll);
        g_aoh[(size_t)(b*SEQ + row0)*512 + widx] = hh;
        g_aol[(size_t)(b*SEQ + row0)*512 + widx] = ll;
        cvt_pack(o[nt][2]*inv1, o[nt][3]*inv1, hh, ll);
        g_aoh[(size_t)(b*SEQ + row0 + 8)*512 + widx] = hh;
        g_aol[(size_t)(b*SEQ + row0 + 8)*512 + widx] = ll;
    }
}

// ---------------- launch ----------------------------------------------------
#define GEMM_SMEM (2*49152)
#define FLASH_SMEM (32768 + 2*32768)

extern "C" void kernel_launch(void* const* d_in, const int* in_sizes, int n_in,
                              void* d_out, int out_size)
{
    const float* x      = (const float*)d_in[0];
    const void*  mask   = d_in[1];
    const float* qkv_w  = (const float*)d_in[2];
    const float* q_nw   = (const float*)d_in[3];
    const float* q_nb   = (const float*)d_in[4];
    const float* k_nw   = (const float*)d_in[5];
    const float* k_nb   = (const float*)d_in[6];
    const float* proj_w = (const float*)d_in[7];
    const float* proj_b = (const float*)d_in[8];
    float* out = (float*)d_out;

    probe_mask_kernel<<<1, 256>>>((const unsigned int*)mask);
    mask_pack_kernel<<<1024, 256>>>(mask);
    convert_all_kernel<<<(NW_X + NW_WQ + NW_PW)/256, 256>>>(x, qkv_w, proj_w);

    cudaFuncSetAttribute(qkv_gemm_ln_kernel,
                         cudaFuncAttributeMaxDynamicSharedMemorySize, GEMM_SMEM);
    qkv_gemm_ln_kernel<<<dim3(48, 32), 256, GEMM_SMEM>>>(q_nw, q_nb, k_nw, k_nb);

    cudaFuncSetAttribute(flash_attn_mma_kernel,
                         cudaFuncAttributeMaxDynamicSharedMemorySize, FLASH_SMEM);
    flash_attn_mma_kernel<<<dim3(16, NHEADS, BATCH), 256, FLASH_SMEM>>>();

    cudaFuncSetAttribute(proj_gemm_kernel,
                         cudaFuncAttributeMaxDynamicSharedMemorySize, GEMM_SMEM);
    proj_gemm_kernel<<<dim3(16, 32), 256, GEMM_SMEM>>>(proj_b, out);
}

// round 16
// speedup vs baseline: 1.0604x; 1.0604x over previous
#include <cuda_runtime.h>
#include <cuda_bf16.h>
#include <math.h>

#define SEQ   2048
#define BATCH 2
#define NHEADS 16
#define HDIM  64
#define MDIM  1024

#define MASKED (-2e30f)
#define MINIT  (-1e30f)

// ---------------- scratch (device globals; no allocations allowed) ----------
__device__ __align__(16) unsigned g_Xh[4096*512],  g_Xl[4096*512];    // X bf16 hi/lo
__device__ __align__(16) unsigned g_Wqh[3072*512], g_Wql[3072*512];   // qkv_w
__device__ __align__(16) unsigned g_Pwh[1024*512], g_Pwl[1024*512];   // proj_w
__device__ __align__(16) unsigned g_qh[65536*32],  g_ql[65536*32];    // (b,h,n) rows of 64 d
__device__ __align__(16) unsigned g_kh[65536*32],  g_kl[65536*32];
__device__ __align__(16) unsigned g_vh[65536*32],  g_vl[65536*32];
__device__ __align__(16) unsigned g_aoh[4096*512], g_aol[4096*512];   // attn out bf16 hi/lo
__device__ unsigned g_mb[4096*64];                                    // mask bits
__device__ int g_mask_kind;

// ---------------- helpers ----------------------------------------------------
__device__ __forceinline__ void cvt_pack(float x0, float x1, unsigned &h, unsigned &l)
{
    __nv_bfloat16 h0 = __float2bfloat16_rn(x0);
    __nv_bfloat16 h1 = __float2bfloat16_rn(x1);
    __nv_bfloat16 l0 = __float2bfloat16_rn(x0 - __bfloat162float(h0));
    __nv_bfloat16 l1 = __float2bfloat16_rn(x1 - __bfloat162float(h1));
    __nv_bfloat162 hp; hp.x = h0; hp.y = h1;
    __nv_bfloat162 lp; lp.x = l0; lp.y = l1;
    h = *reinterpret_cast<unsigned*>(&hp);
    l = *reinterpret_cast<unsigned*>(&lp);
}

__device__ __forceinline__ void mma_bf16(float* c, const unsigned* a, const unsigned* b)
{
    asm volatile(
        "mma.sync.aligned.m16n8k16.row.col.f32.bf16.bf16.f32 "
        "{%0,%1,%2,%3},{%4,%5,%6,%7},{%8,%9},{%0,%1,%2,%3};"
        : "+f"(c[0]), "+f"(c[1]), "+f"(c[2]), "+f"(c[3])
        : "r"(a[0]), "r"(a[1]), "r"(a[2]), "r"(a[3]), "r"(b[0]), "r"(b[1]));
}

__device__ __forceinline__ void cp16(unsigned dst, const void* src)
{
    asm volatile("cp.async.cg.shared.global [%0], [%1], 16;" :: "r"(dst), "l"(src));
}
__device__ __forceinline__ void cp_commit() { asm volatile("cp.async.commit_group;"); }
template<int N> __device__ __forceinline__ void cp_wait()
{ asm volatile("cp.async.wait_group %0;" :: "n"(N)); }

__device__ __forceinline__ void ldsm4(unsigned a, unsigned &r0, unsigned &r1,
                                      unsigned &r2, unsigned &r3)
{
    asm volatile("ldmatrix.sync.aligned.m8n8.x4.shared.b16 {%0,%1,%2,%3}, [%4];"
        : "=r"(r0), "=r"(r1), "=r"(r2), "=r"(r3) : "r"(a));
}
__device__ __forceinline__ void ldsm4t(unsigned a, unsigned &r0, unsigned &r1,
                                       unsigned &r2, unsigned &r3)
{
    asm volatile("ldmatrix.sync.aligned.m8n8.x4.trans.shared.b16 {%0,%1,%2,%3}, [%4];"
        : "=r"(r0), "=r"(r1), "=r"(r2), "=r"(r3) : "r"(a));
}

// ---------------- prep kernels ----------------------------------------------
__global__ void probe_mask_kernel(const unsigned int* __restrict__ m)
{
    __shared__ int s_ni, s_nf;
    if (threadIdx.x == 0) { s_ni = 0; s_nf = 0; }
    __syncthreads();
    int ni = 0, nf = 0;
    for (int i = threadIdx.x; i < 4096; i += 256) {
        unsigned w = m[i];
        if (w > 1u) ni = 1;
        if (w != 0u && w != 0x3F800000u) nf = 1;
    }
    if (ni) atomicOr(&s_ni, 1);
    if (nf) atomicOr(&s_nf, 1);
    __syncthreads();
    if (threadIdx.x == 0)
        g_mask_kind = (s_ni == 0) ? 0 : (s_nf == 0) ? 2 : 1;
}

__global__ void mask_pack_kernel(const void* __restrict__ maskp)
{
    int w = blockIdx.x*256 + threadIdx.x;
    int word = w & 63, row = w >> 6;
    size_t off = (size_t)row*SEQ + word*32;
    unsigned bits = 0;
    if (g_mask_kind == 1) {
        const uchar4* p = (const uchar4*)((const unsigned char*)maskp + off);
#pragma unroll
        for (int i = 0; i < 8; i++) {
            uchar4 u4 = p[i];
            bits |= (u4.x ? 1u : 0u) << (i*4);
            bits |= (u4.y ? 1u : 0u) << (i*4+1);
            bits |= (u4.z ? 1u : 0u) << (i*4+2);
            bits |= (u4.w ? 1u : 0u) << (i*4+3);
        }
    } else {
        const uint4* p = (const uint4*)((const unsigned*)maskp + off);
#pragma unroll
        for (int i = 0; i < 8; i++) {
            uint4 u4 = p[i];
            bits |= (u4.x ? 1u : 0u) << (i*4);
            bits |= (u4.y ? 1u : 0u) << (i*4+1);
            bits |= (u4.z ? 1u : 0u) << (i*4+2);
            bits |= (u4.w ? 1u : 0u) << (i*4+3);
        }
    }
    g_mb[w] = bits;
}

#define NW_X   (4096*512)
#define NW_WQ  (3072*512)
#define NW_PW  (1024*512)
__global__ void convert_all_kernel(const float* __restrict__ x,
                                   const float* __restrict__ qkv_w,
                                   const float* __restrict__ proj_w)
{
    int i = blockIdx.x*256 + threadIdx.x;
    const float* src; unsigned *H, *L; int idx;
    if (i < NW_X)                 { src = x;      H = g_Xh;  L = g_Xl;  idx = i; }
    else if (i < NW_X + NW_WQ)    { src = qkv_w;  H = g_Wqh; L = g_Wql; idx = i - NW_X; }
    else                          { src = proj_w; H = g_Pwh; L = g_Pwl; idx = i - NW_X - NW_WQ; }
    float2 v = ((const float2*)src)[idx];
    unsigned h, l;
    cvt_pack(v.x, v.y, h, l);
    H[idx] = h; L[idx] = l;
}

// ---------------- GEMM mainloop: 128 thr, BM=64 BN=64 BK=32, 4 CTA/SM -------
// stage = A 64x128B (8KB, chunks 0-3 hi / 4-7 lo) + B 64x128B (8KB) = 16KB; x2.
// warps 2x2, warp tile 32x32 -> identical per-warp intensity to the 256-thr
// version (16 LDSM : 48 HMMA per 32-k), but 16 warps/SM for latency hiding.
__device__ __forceinline__ void gemm_mainloop(
    const unsigned* __restrict__ Agh, const unsigned* __restrict__ Agl,
    const unsigned* __restrict__ Bgh, const unsigned* __restrict__ Bgl,
    unsigned* sm, int m0, int n0, float acc[2][4][4])
{
    const int tid = threadIdx.x;
    const int lane = tid & 31, warp = tid >> 5;
    const int warp_m = warp >> 1, warp_n = warp & 1;
    unsigned smb = (unsigned)__cvta_generic_to_shared(sm);

    auto stage = [&](int it, int buf) {
        unsigned ab = smb + buf*16384;
        unsigned bb = ab + 8192;
#pragma unroll
        for (int u = 0; u < 4; u++) {
            int ci = tid + u*128;             // 0..511: A chunks
            int row = ci >> 3, cc = ci & 7, hl = cc >> 2, c = cc & 3;
            const unsigned* src = (hl ? Agl : Agh) + (size_t)(m0+row)*512 + it*16 + c*4;
            cp16(ab + row*128 + ((cc ^ (row&7))<<4), src);
        }
#pragma unroll
        for (int u = 0; u < 4; u++) {
            int ci = tid + u*128;             // 0..511: B chunks
            int row = ci >> 3, cc = ci & 7, hl = cc >> 2, c = cc & 3;
            const unsigned* src = (hl ? Bgl : Bgh) + (size_t)(n0+row)*512 + it*16 + c*4;
            cp16(bb + row*128 + ((cc ^ (row&7))<<4), src);
        }
    };

    stage(0, 0); cp_commit();

    for (int it = 0; it < 32; it++) {
        cp_wait<0>();
        __syncthreads();
        if (it + 1 < 32) { stage(it+1, (it+1)&1); cp_commit(); }

        unsigned ab = smb + (it&1)*16384;
        unsigned bb = ab + 8192;
#pragma unroll
        for (int ks = 0; ks < 2; ks++) {
            unsigned ah[2][4], al[2][4], bh[4][2], bl[4][2];
#pragma unroll
            for (int mt = 0; mt < 2; mt++) {
                int row = warp_m*32 + mt*16 + (lane & 15);
                int ch = 2*ks + (lane >> 4);
                ldsm4(ab + row*128 + ((ch       ^ (row&7))<<4),
                      ah[mt][0], ah[mt][1], ah[mt][2], ah[mt][3]);
                ldsm4(ab + row*128 + (((ch + 4) ^ (row&7))<<4),
                      al[mt][0], al[mt][1], al[mt][2], al[mt][3]);
            }
#pragma unroll
            for (int ntp = 0; ntp < 2; ntp++) {
                int row = warp_n*32 + ntp*16 + (lane & 7) + ((lane & 16) >> 1);
                int ch = 2*ks + ((lane >> 3) & 1);
                unsigned r0, r1, r2, r3;
                ldsm4(bb + row*128 + ((ch ^ (row&7))<<4), r0, r1, r2, r3);
                bh[2*ntp][0] = r0; bh[2*ntp][1] = r1;
                bh[2*ntp+1][0] = r2; bh[2*ntp+1][1] = r3;
                ldsm4(bb + row*128 + (((ch + 4) ^ (row&7))<<4), r0, r1, r2, r3);
                bl[2*ntp][0] = r0; bl[2*ntp][1] = r1;
                bl[2*ntp+1][0] = r2; bl[2*ntp+1][1] = r3;
            }
#pragma unroll
            for (int mt = 0; mt < 2; mt++)
#pragma unroll
                for (int nt = 0; nt < 4; nt++) {
                    mma_bf16(acc[mt][nt], ah[mt], bh[nt]);
                    mma_bf16(acc[mt][nt], ah[mt], bl[nt]);
                    mma_bf16(acc[mt][nt], al[mt], bh[nt]);
                }
        }
    }
}

// packed bf16 hi/lo pair store for LN/V epilogue
__device__ __forceinline__ void pack_store_pair(
    unsigned* __restrict__ H, unsigned* __restrict__ L,
    size_t wbase, int lane, float y1, float y2)
{
    float y1o = __shfl_xor_sync(0xffffffffu, y1, 1);
    float y2o = __shfl_xor_sync(0xffffffffu, y2, 1);
    if (!(lane & 1)) {
        unsigned h1, l1, h2, l2;
        cvt_pack(y1, y1o, h1, l1);
        cvt_pack(y2, y2o, h2, l2);
        H[wbase + (lane>>1)]      = h1;
        H[wbase + 16 + (lane>>1)] = h2;
        L[wbase + (lane>>1)]      = l1;
        L[wbase + 16 + (lane>>1)] = l2;
    }
}

// ---------------- kernel 1: QKV GEMM + fused layernorm -> packed bf16 -------
// grid (48, 64): n-block 64 = one (s, head); m-block 64 rows.
// q is additionally scaled by 0.125 * log2(e) so flash can use exp2.
#define QSCALE 0.18033688011112042f
__global__ __launch_bounds__(128, 4) void qkv_gemm_ln_kernel(
    const float* __restrict__ qw, const float* __restrict__ qb,
    const float* __restrict__ kw, const float* __restrict__ kb)
{
    __shared__ __align__(16) unsigned sm[8192];   // 32KB: 2 stages / epilogue tile
    const int tid = threadIdx.x;
    const int m0 = blockIdx.y * 64, n0 = blockIdx.x * 64;
    const int warp = tid >> 5, lane = tid & 31;
    const int warp_m = warp >> 1, warp_n = warp & 1;
    const int group = lane >> 2, tg = lane & 3;

    float acc[2][4][4];
#pragma unroll
    for (int mt = 0; mt < 2; mt++)
#pragma unroll
        for (int nt = 0; nt < 4; nt++)
#pragma unroll
            for (int j = 0; j < 4; j++) acc[mt][nt][j] = 0.f;

    gemm_mainloop(g_Xh, g_Xl, g_Wqh, g_Wql, sm, m0, n0, acc);

    const int s = n0 >> 10;
    const int h = (n0 & 1023) >> 6;
    float* et = (float*)sm;                       // [64][66] = 16.9KB

    __syncthreads();
#pragma unroll
    for (int mt = 0; mt < 2; mt++)
#pragma unroll
        for (int nt = 0; nt < 4; nt++) {
            int r0 = warp_m*32 + mt*16 + group;
            int col = warp_n*32 + nt*8 + 2*tg;
            *(float2*)&et[r0*66 + col] =
                make_float2(acc[mt][nt][0], acc[mt][nt][1]);
            *(float2*)&et[(r0+8)*66 + col] =
                make_float2(acc[mt][nt][2], acc[mt][nt][3]);
        }
    __syncthreads();
#pragma unroll
    for (int rr = 0; rr < 16; rr++) {
        int r  = warp*16 + rr;
        int gm = m0 + r;
        int bb = gm >> 11, n = gm & 2047;
        float v1 = et[r*66 + lane];
        float v2 = et[r*66 + lane + 32];
        size_t wbase = (((size_t)(bb*NHEADS + h))*SEQ + n)*32;
        if (s == 2) {
            pack_store_pair(g_vh, g_vl, wbase, lane, v1, v2);
        } else {
            float sum = v1 + v2, sq = v1*v1 + v2*v2;
#pragma unroll
            for (int o = 16; o; o >>= 1) {
                sum += __shfl_xor_sync(0xffffffffu, sum, o);
                sq  += __shfl_xor_sync(0xffffffffu, sq,  o);
            }
            float mean = sum * (1.f/64.f);
            float var  = sq  * (1.f/64.f) - mean*mean;
            float rstd = rsqrtf(var + 1e-5f);
            if (s == 0) {
                float y1 = ((v1-mean)*rstd*qw[lane]    + qb[lane])    * QSCALE;
                float y2 = ((v2-mean)*rstd*qw[lane+32] + qb[lane+32]) * QSCALE;
                pack_store_pair(g_qh, g_ql, wbase, lane, y1, y2);
            } else {
                float y1 = (v1-mean)*rstd*kw[lane]    + kb[lane];
                float y2 = (v2-mean)*rstd*kw[lane+32] + kb[lane+32];
                pack_store_pair(g_kh, g_kl, wbase, lane, y1, y2);
            }
        }
    }
}

// ---------------- kernel 3: output projection + bias ------------------------
// grid (16, 64)
__global__ __launch_bounds__(128, 4) void proj_gemm_kernel(
    const float* __restrict__ bias, float* __restrict__ out)
{
    __shared__ __align__(16) unsigned sm[8192];
    const int tid = threadIdx.x;
    const int m0 = blockIdx.y * 64, n0 = blockIdx.x * 64;
    const int warp = tid >> 5, lane = tid & 31;
    const int warp_m = warp >> 1, warp_n = warp & 1;
    const int group = lane >> 2, tg = lane & 3;

    float acc[2][4][4];
#pragma unroll
    for (int mt = 0; mt < 2; mt++)
#pragma unroll
        for (int nt = 0; nt < 4; nt++)
#pragma unroll
            for (int j = 0; j < 4; j++) acc[mt][nt][j] = 0.f;

    gemm_mainloop(g_aoh, g_aol, g_Pwh, g_Pwl, sm, m0, n0, acc);

#pragma unroll
    for (int nt = 0; nt < 4; nt++) {
        int col = n0 + warp_n*32 + nt*8 + 2*tg;
        float b0 = bias[col], b1 = bias[col+1];
#pragma unroll
        for (int mt = 0; mt < 2; mt++) {
            int row = m0 + warp_m*32 + mt*16 + group;
            *(float2*)(out + (size_t)row*MDIM + col) =
                make_float2(acc[mt][nt][0] + b0, acc[mt][nt][1] + b1);
            *(float2*)(out + (size_t)(row+8)*MDIM + col) =
                make_float2(acc[mt][nt][2] + b0, acc[mt][nt][3] + b1);
        }
    }
}

// ---------------- kernel 2: flash attention (R14 best: 2 CTAs/SM) -----------
__global__ __launch_bounds__(256, 2) void flash_attn_mma_kernel()
{
    extern __shared__ __align__(16) unsigned fsm[];
    const int tid = threadIdx.x;
    const int warp = tid >> 5, lane = tid & 31;
    const int group = lane >> 2, tg = lane & 3;
    const int q0 = blockIdx.x * 128, h = blockIdx.y, b = blockIdx.z;
    const int bhrow = (b*NHEADS + h)*SEQ;
    unsigned smb = (unsigned)__cvta_generic_to_shared(fsm);
    const unsigned kvb0 = smb + 32768;        // KV buffers base

    // ---- stage Q tile (persistent: hi at +0, lo at +16KB) ----
#pragma unroll
    for (int u = 0; u < 8; u++) {
        int ci = tid + u*256;
        int hl = ci >> 10, wi = ci & 1023;
        int row = wi >> 3, c = wi & 7;
        const unsigned* src = (hl ? g_ql : g_qh) + (size_t)(bhrow + q0 + row)*32 + c*4;
        cp16(smb + hl*16384 + row*128 + ((c ^ (row&7))<<4), src);
    }
    cp_commit();

    auto stageKV = [&](int kt, int buf) {
        unsigned base = kvb0 + buf*32768;
#pragma unroll
        for (int u = 0; u < 8; u++) {
            int ci = tid + u*256;
            int arr = ci >> 9, wi = ci & 511;
            int row = wi >> 3, c = wi & 7;
            const unsigned* sa;
            if (arr == 0) sa = g_kh; else if (arr == 1) sa = g_kl;
            else if (arr == 2) sa = g_vh; else sa = g_vl;
            const unsigned* src = sa + (size_t)(bhrow + kt*64 + row)*32 + c*4;
            cp16(base + arr*8192 + row*128 + ((c ^ (row&7))<<4), src);
        }
    };

    stageKV(0, 0); cp_commit();

    float m0r = MINIT, m1r = MINIT, l0r = 0.f, l1r = 0.f;
    float o[8][4];
#pragma unroll
    for (int nt = 0; nt < 8; nt++)
#pragma unroll
        for (int j = 0; j < 4; j++) o[nt][j] = 0.f;

    const int lr = warp*16 + group;
    const unsigned* mb0 = g_mb + (size_t)(b*SEQ + q0 + lr)*64;
    const unsigned* mb1 = g_mb + (size_t)(b*SEQ + q0 + lr + 8)*64;

    for (int kt = 0; kt < SEQ/64; kt++) {
        unsigned w0lo = mb0[kt*2], w0hi = mb0[kt*2+1];
        unsigned w1lo = mb1[kt*2], w1hi = mb1[kt*2+1];
        cp_wait<0>();
        __syncthreads();
        if (kt + 1 < SEQ/64) { stageKV(kt+1, (kt+1)&1); cp_commit(); }

        unsigned kb = kvb0 + (kt&1)*32768;

        // ---- S = Q K^T (bf16x3); Q frags re-loaded from smem per ks ----
        float s[8][4];
#pragma unroll
        for (int nt = 0; nt < 8; nt++)
#pragma unroll
            for (int j = 0; j < 4; j++) s[nt][j] = 0.f;
#pragma unroll
        for (int ks = 0; ks < 4; ks++) {
            unsigned qhf[4], qlf[4];
            {
                int row = warp*16 + (lane & 15);
                int ch = 2*ks + (lane >> 4);
                unsigned a = row*128 + ((ch ^ (row&7))<<4);
                ldsm4(smb + a,         qhf[0], qhf[1], qhf[2], qhf[3]);
                ldsm4(smb + 16384 + a, qlf[0], qlf[1], qlf[2], qlf[3]);
            }
#pragma unroll
            for (int ntp = 0; ntp < 4; ntp++) {
                int row = ntp*16 + (lane & 7) + ((lane & 16) >> 1);
                int ch = 2*ks + ((lane >> 3) & 1);
                unsigned a = kb + row*128 + ((ch ^ (row&7))<<4);
                unsigned bh0[2], bh1[2], bl0[2], bl1[2];
                ldsm4(a,        bh0[0], bh0[1], bh1[0], bh1[1]);
                ldsm4(a + 8192, bl0[0], bl0[1], bl1[0], bl1[1]);
                mma_bf16(s[2*ntp],   qhf, bh0);
                mma_bf16(s[2*ntp],   qhf, bl0);
                mma_bf16(s[2*ntp],   qlf, bh0);
                mma_bf16(s[2*ntp+1], qhf, bh1);
                mma_bf16(s[2*ntp+1], qhf, bl1);
                mma_bf16(s[2*ntp+1], qlf, bh1);
            }
        }

        // ---- mask + online softmax (base-2) ----
        float rm0 = MINIT, rm1 = MINIT;
#pragma unroll
        for (int nt = 0; nt < 8; nt++) {
            int kidx = nt*8 + 2*tg;
            unsigned wr0 = (nt < 4) ? w0lo : w0hi;
            unsigned wr1 = (nt < 4) ? w1lo : w1hi;
            int sh = kidx & 31;
            if ((wr0 >> sh) & 1)     s[nt][0] = MASKED;
            if ((wr0 >> (sh+1)) & 1) s[nt][1] = MASKED;
            if ((wr1 >> sh) & 1)     s[nt][2] = MASKED;
            if ((wr1 >> (sh+1)) & 1) s[nt][3] = MASKED;
            rm0 = fmaxf(rm0, fmaxf(s[nt][0], s[nt][1]));
            rm1 = fmaxf(rm1, fmaxf(s[nt][2], s[nt][3]));
        }
        rm0 = fmaxf(rm0, __shfl_xor_sync(0xffffffffu, rm0, 1));
        rm0 = fmaxf(rm0, __shfl_xor_sync(0xffffffffu, rm0, 2));
        rm1 = fmaxf(rm1, __shfl_xor_sync(0xffffffffu, rm1, 1));
        rm1 = fmaxf(rm1, __shfl_xor_sync(0xffffffffu, rm1, 2));
        float mn0 = fmaxf(m0r, rm0), mn1 = fmaxf(m1r, rm1);
        float c0 = exp2f(m0r - mn0), c1 = exp2f(m1r - mn1);
        m0r = mn0; m1r = mn1;

        float ls0 = 0.f, ls1 = 0.f;
#pragma unroll
        for (int nt = 0; nt < 8; nt++) {
            s[nt][0] = exp2f(s[nt][0] - mn0);
            s[nt][1] = exp2f(s[nt][1] - mn0);
            s[nt][2] = exp2f(s[nt][2] - mn1);
            s[nt][3] = exp2f(s[nt][3] - mn1);
            ls0 += s[nt][0] + s[nt][1];
            ls1 += s[nt][2] + s[nt][3];
        }
        ls0 += __shfl_xor_sync(0xffffffffu, ls0, 1);
        ls0 += __shfl_xor_sync(0xffffffffu, ls0, 2);
        ls1 += __shfl_xor_sync(0xffffffffu, ls1, 1);
        ls1 += __shfl_xor_sync(0xffffffffu, ls1, 2);
        l0r = l0r*c0 + ls0;
        l1r = l1r*c1 + ls1;
#pragma unroll
        for (int nt = 0; nt < 8; nt++) {
            o[nt][0] *= c0; o[nt][1] *= c0;
            o[nt][2] *= c1; o[nt][3] *= c1;
        }

        // ---- P fragments from S accumulators ----
        unsigned ph[4][4], pl[4][4];
#pragma unroll
        for (int j = 0; j < 4; j++) {
            cvt_pack(s[2*j][0],   s[2*j][1],   ph[j][0], pl[j][0]);
            cvt_pack(s[2*j][2],   s[2*j][3],   ph[j][1], pl[j][1]);
            cvt_pack(s[2*j+1][0], s[2*j+1][1], ph[j][2], pl[j][2]);
            cvt_pack(s[2*j+1][2], s[2*j+1][3], ph[j][3], pl[j][3]);
        }

        // ---- O += P V (V via ldmatrix.trans) ----
        unsigned vb = kb + 16384;
#pragma unroll
        for (int nt = 0; nt < 8; nt++) {
#pragma unroll
            for (int jp = 0; jp < 2; jp++) {
                int row = jp*32 + lane;
                unsigned a = vb + row*128 + ((nt ^ (row&7))<<4);
                unsigned vh0[2], vh1[2], vl0[2], vl1[2];
                ldsm4t(a,        vh0[0], vh0[1], vh1[0], vh1[1]);
                ldsm4t(a + 8192, vl0[0], vl0[1], vl1[0], vl1[1]);
                mma_bf16(o[nt], ph[2*jp],   vh0);
                mma_bf16(o[nt], ph[2*jp],   vl0);
                mma_bf16(o[nt], pl[2*jp],   vh0);
                mma_bf16(o[nt], ph[2*jp+1], vh1);
                mma_bf16(o[nt], ph[2*jp+1], vl1);
                mma_bf16(o[nt], pl[2*jp+1], vh1);
            }
        }
    }

    // ---- finalize: pack to bf16 hi/lo ao ----
    const int row0 = q0 + warp*16 + group;
    float inv0 = 1.f / l0r, inv1 = 1.f / l1r;
#pragma unroll
    for (int nt = 0; nt < 8; nt++) {
        int widx = h*32 + nt*4 + tg;
        unsigned hh, ll;
        cvt_pack(o[nt][0]*inv0, o[nt][1]*inv0, hh, ll);
        g_aoh[(size_t)(b*SEQ + row0)*512 + widx] = hh;
        g_aol[(size_t)(b*SEQ + row0)*512 + widx] = ll;
        cvt_pack(o[nt][2]*inv1, o[nt][3]*inv1, hh, ll);
        g_aoh[(size_t)(b*SEQ + row0 + 8)*512 + widx] = hh;
        g_aol[(size_t)(b*SEQ + row0 + 8)*512 + widx] = ll;
    }
}

// ---------------- launch ----------------------------------------------------
#define FLASH_SMEM (32768 + 2*32768)

extern "C" void kernel_launch(void* const* d_in, const int* in_sizes, int n_in,
                              void* d_out, int out_size)
{
    const float* x      = (const float*)d_in[0];
    const void*  mask   = d_in[1];
    const float* qkv_w  = (const float*)d_in[2];
    const float* q_nw   = (const float*)d_in[3];
    const float* q_nb   = (const float*)d_in[4];
    const float* k_nw   = (const float*)d_in[5];
    const float* k_nb   = (const float*)d_in[6];
    const float* proj_w = (const float*)d_in[7];
    const float* proj_b = (const float*)d_in[8];
    float* out = (float*)d_out;

    probe_mask_kernel<<<1, 256>>>((const unsigned int*)mask);
    mask_pack_kernel<<<1024, 256>>>(mask);
    convert_all_kernel<<<(NW_X + NW_WQ + NW_PW)/256, 256>>>(x, qkv_w, proj_w);

    qkv_gemm_ln_kernel<<<dim3(48, 64), 128>>>(q_nw, q_nb, k_nw, k_nb);

    cudaFuncSetAttribute(flash_attn_mma_kernel,
                         cudaFuncAttributeMaxDynamicSharedMemorySize, FLASH_SMEM);
    flash_attn_mma_kernel<<<dim3(16, NHEADS, BATCH), 256, FLASH_SMEM>>>();

    proj_gemm_kernel<<<dim3(16, 64), 128>>>(proj_b, out);
}

// round 17
// speedup vs baseline: 1.0624x; 1.0019x over previous
#include <cuda_runtime.h>
#include <cuda_bf16.h>
#include <math.h>

#define SEQ   2048
#define BATCH 2
#define NHEADS 16
#define HDIM  64
#define MDIM  1024

#define MASKED (-2e30f)
#define MINIT  (-1e30f)

// ---------------- scratch (device globals; no allocations allowed) ----------
__device__ __align__(16) unsigned g_Xh[4096*512],  g_Xl[4096*512];    // X bf16 hi/lo
__device__ __align__(16) unsigned g_Wqh[3072*512], g_Wql[3072*512];   // qkv_w
__device__ __align__(16) unsigned g_Pwh[1024*512], g_Pwl[1024*512];   // proj_w
__device__ __align__(16) unsigned g_qh[65536*32],  g_ql[65536*32];    // (b,h,n) rows of 64 d
__device__ __align__(16) unsigned g_kh[65536*32],  g_kl[65536*32];
__device__ __align__(16) unsigned g_vh[65536*32],  g_vl[65536*32];
__device__ __align__(16) unsigned g_aoh[4096*512], g_aol[4096*512];   // attn out bf16 hi/lo
__device__ unsigned g_mb[4096*64];                                    // mask bits
__device__ int g_mask_kind;

// ---------------- helpers ----------------------------------------------------
__device__ __forceinline__ void cvt_pack(float x0, float x1, unsigned &h, unsigned &l)
{
    __nv_bfloat16 h0 = __float2bfloat16_rn(x0);
    __nv_bfloat16 h1 = __float2bfloat16_rn(x1);
    __nv_bfloat16 l0 = __float2bfloat16_rn(x0 - __bfloat162float(h0));
    __nv_bfloat16 l1 = __float2bfloat16_rn(x1 - __bfloat162float(h1));
    __nv_bfloat162 hp; hp.x = h0; hp.y = h1;
    __nv_bfloat162 lp; lp.x = l0; lp.y = l1;
    h = *reinterpret_cast<unsigned*>(&hp);
    l = *reinterpret_cast<unsigned*>(&lp);
}

__device__ __forceinline__ void mma_bf16(float* c, const unsigned* a, const unsigned* b)
{
    asm volatile(
        "mma.sync.aligned.m16n8k16.row.col.f32.bf16.bf16.f32 "
        "{%0,%1,%2,%3},{%4,%5,%6,%7},{%8,%9},{%0,%1,%2,%3};"
        : "+f"(c[0]), "+f"(c[1]), "+f"(c[2]), "+f"(c[3])
        : "r"(a[0]), "r"(a[1]), "r"(a[2]), "r"(a[3]), "r"(b[0]), "r"(b[1]));
}

__device__ __forceinline__ void cp16(unsigned dst, const void* src)
{
    asm volatile("cp.async.cg.shared.global [%0], [%1], 16;" :: "r"(dst), "l"(src));
}
__device__ __forceinline__ void cp_commit() { asm volatile("cp.async.commit_group;"); }
template<int N> __device__ __forceinline__ void cp_wait()
{ asm volatile("cp.async.wait_group %0;" :: "n"(N)); }

__device__ __forceinline__ void ldsm4(unsigned a, unsigned &r0, unsigned &r1,
                                      unsigned &r2, unsigned &r3)
{
    asm volatile("ldmatrix.sync.aligned.m8n8.x4.shared.b16 {%0,%1,%2,%3}, [%4];"
        : "=r"(r0), "=r"(r1), "=r"(r2), "=r"(r3) : "r"(a));
}
__device__ __forceinline__ void ldsm4t(unsigned a, unsigned &r0, unsigned &r1,
                                       unsigned &r2, unsigned &r3)
{
    asm volatile("ldmatrix.sync.aligned.m8n8.x4.trans.shared.b16 {%0,%1,%2,%3}, [%4];"
        : "=r"(r0), "=r"(r1), "=r"(r2), "=r"(r3) : "r"(a));
}

// ---------------- prep kernels ----------------------------------------------
__global__ void probe_mask_kernel(const unsigned int* __restrict__ m)
{
    __shared__ int s_ni, s_nf;
    if (threadIdx.x == 0) { s_ni = 0; s_nf = 0; }
    __syncthreads();
    int ni = 0, nf = 0;
    for (int i = threadIdx.x; i < 4096; i += 256) {
        unsigned w = m[i];
        if (w > 1u) ni = 1;
        if (w != 0u && w != 0x3F800000u) nf = 1;
    }
    if (ni) atomicOr(&s_ni, 1);
    if (nf) atomicOr(&s_nf, 1);
    __syncthreads();
    if (threadIdx.x == 0)
        g_mask_kind = (s_ni == 0) ? 0 : (s_nf == 0) ? 2 : 1;
}

// fused prep: bf16 hi/lo conversion of x/qkv_w/proj_w AND mask bit-packing
#define NW_X   (4096*512)
#define NW_WQ  (3072*512)
#define NW_PW  (1024*512)
#define NW_ALL (NW_X + NW_WQ + NW_PW)
#define NMASKW (4096*64)
__global__ void prep_all_kernel(const float* __restrict__ x,
                                const float* __restrict__ qkv_w,
                                const float* __restrict__ proj_w,
                                const void* __restrict__ maskp)
{
    int i = blockIdx.x*256 + threadIdx.x;
    if (i < NW_ALL) {
        const float* src; unsigned *H, *L; int idx;
        if (i < NW_X)              { src = x;      H = g_Xh;  L = g_Xl;  idx = i; }
        else if (i < NW_X + NW_WQ) { src = qkv_w;  H = g_Wqh; L = g_Wql; idx = i - NW_X; }
        else                       { src = proj_w; H = g_Pwh; L = g_Pwl; idx = i - NW_X - NW_WQ; }
        float2 v = ((const float2*)src)[idx];
        unsigned h, l;
        cvt_pack(v.x, v.y, h, l);
        H[idx] = h; L[idx] = l;
    } else {
        int w = i - NW_ALL;
        if (w < NMASKW) {
            int word = w & 63, row = w >> 6;
            size_t off = (size_t)row*SEQ + word*32;
            unsigned bits = 0;
            if (g_mask_kind == 1) {
                const uchar4* p = (const uchar4*)((const unsigned char*)maskp + off);
#pragma unroll
                for (int k = 0; k < 8; k++) {
                    uchar4 u4 = p[k];
                    bits |= (u4.x ? 1u : 0u) << (k*4);
                    bits |= (u4.y ? 1u : 0u) << (k*4+1);
                    bits |= (u4.z ? 1u : 0u) << (k*4+2);
                    bits |= (u4.w ? 1u : 0u) << (k*4+3);
                }
            } else {
                const uint4* p = (const uint4*)((const unsigned*)maskp + off);
#pragma unroll
                for (int k = 0; k < 8; k++) {
                    uint4 u4 = p[k];
                    bits |= (u4.x ? 1u : 0u) << (k*4);
                    bits |= (u4.y ? 1u : 0u) << (k*4+1);
                    bits |= (u4.z ? 1u : 0u) << (k*4+2);
                    bits |= (u4.w ? 1u : 0u) << (k*4+3);
                }
            }
            g_mb[w] = bits;
        }
    }
}

// ---------------- GEMM mainloop: 128 thr, BM=64 BN=64 BK=32, 4 CTA/SM -------
__device__ __forceinline__ void gemm_mainloop(
    const unsigned* __restrict__ Agh, const unsigned* __restrict__ Agl,
    const unsigned* __restrict__ Bgh, const unsigned* __restrict__ Bgl,
    unsigned* sm, int m0, int n0, float acc[2][4][4])
{
    const int tid = threadIdx.x;
    const int lane = tid & 31, warp = tid >> 5;
    const int warp_m = warp >> 1, warp_n = warp & 1;
    unsigned smb = (unsigned)__cvta_generic_to_shared(sm);

    auto stage = [&](int it, int buf) {
        unsigned ab = smb + buf*16384;
        unsigned bb = ab + 8192;
#pragma unroll
        for (int u = 0; u < 4; u++) {
            int ci = tid + u*128;
            int row = ci >> 3, cc = ci & 7, hl = cc >> 2, c = cc & 3;
            const unsigned* src = (hl ? Agl : Agh) + (size_t)(m0+row)*512 + it*16 + c*4;
            cp16(ab + row*128 + ((cc ^ (row&7))<<4), src);
        }
#pragma unroll
        for (int u = 0; u < 4; u++) {
            int ci = tid + u*128;
            int row = ci >> 3, cc = ci & 7, hl = cc >> 2, c = cc & 3;
            const unsigned* src = (hl ? Bgl : Bgh) + (size_t)(n0+row)*512 + it*16 + c*4;
            cp16(bb + row*128 + ((cc ^ (row&7))<<4), src);
        }
    };

    stage(0, 0); cp_commit();

    for (int it = 0; it < 32; it++) {
        cp_wait<0>();
        __syncthreads();
        if (it + 1 < 32) { stage(it+1, (it+1)&1); cp_commit(); }

        unsigned ab = smb + (it&1)*16384;
        unsigned bb = ab + 8192;
#pragma unroll
        for (int ks = 0; ks < 2; ks++) {
            unsigned ah[2][4], al[2][4], bh[4][2], bl[4][2];
#pragma unroll
            for (int mt = 0; mt < 2; mt++) {
                int row = warp_m*32 + mt*16 + (lane & 15);
                int ch = 2*ks + (lane >> 4);
                ldsm4(ab + row*128 + ((ch       ^ (row&7))<<4),
                      ah[mt][0], ah[mt][1], ah[mt][2], ah[mt][3]);
                ldsm4(ab + row*128 + (((ch + 4) ^ (row&7))<<4),
                      al[mt][0], al[mt][1], al[mt][2], al[mt][3]);
            }
#pragma unroll
            for (int ntp = 0; ntp < 2; ntp++) {
                int row = warp_n*32 + ntp*16 + (lane & 7) + ((lane & 16) >> 1);
                int ch = 2*ks + ((lane >> 3) & 1);
                unsigned r0, r1, r2, r3;
                ldsm4(bb + row*128 + ((ch ^ (row&7))<<4), r0, r1, r2, r3);
                bh[2*ntp][0] = r0; bh[2*ntp][1] = r1;
                bh[2*ntp+1][0] = r2; bh[2*ntp+1][1] = r3;
                ldsm4(bb + row*128 + (((ch + 4) ^ (row&7))<<4), r0, r1, r2, r3);
                bl[2*ntp][0] = r0; bl[2*ntp][1] = r1;
                bl[2*ntp+1][0] = r2; bl[2*ntp+1][1] = r3;
            }
#pragma unroll
            for (int mt = 0; mt < 2; mt++)
#pragma unroll
                for (int nt = 0; nt < 4; nt++) {
                    mma_bf16(acc[mt][nt], ah[mt], bh[nt]);
                    mma_bf16(acc[mt][nt], ah[mt], bl[nt]);
                    mma_bf16(acc[mt][nt], al[mt], bh[nt]);
                }
        }
    }
}

// packed bf16 hi/lo pair store for LN/V epilogue
__device__ __forceinline__ void pack_store_pair(
    unsigned* __restrict__ H, unsigned* __restrict__ L,
    size_t wbase, int lane, float y1, float y2)
{
    float y1o = __shfl_xor_sync(0xffffffffu, y1, 1);
    float y2o = __shfl_xor_sync(0xffffffffu, y2, 1);
    if (!(lane & 1)) {
        unsigned h1, l1, h2, l2;
        cvt_pack(y1, y1o, h1, l1);
        cvt_pack(y2, y2o, h2, l2);
        H[wbase + (lane>>1)]      = h1;
        H[wbase + 16 + (lane>>1)] = h2;
        L[wbase + (lane>>1)]      = l1;
        L[wbase + 16 + (lane>>1)] = l2;
    }
}

// ---------------- kernel 1: QKV GEMM + fused layernorm -> packed bf16 -------
#define QSCALE 0.18033688011112042f
__global__ __launch_bounds__(128, 4) void qkv_gemm_ln_kernel(
    const float* __restrict__ qw, const float* __restrict__ qb,
    const float* __restrict__ kw, const float* __restrict__ kb)
{
    __shared__ __align__(16) unsigned sm[8192];
    const int tid = threadIdx.x;
    const int m0 = blockIdx.y * 64, n0 = blockIdx.x * 64;
    const int warp = tid >> 5, lane = tid & 31;
    const int warp_m = warp >> 1, warp_n = warp & 1;
    const int group = lane >> 2, tg = lane & 3;

    float acc[2][4][4];
#pragma unroll
    for (int mt = 0; mt < 2; mt++)
#pragma unroll
        for (int nt = 0; nt < 4; nt++)
#pragma unroll
            for (int j = 0; j < 4; j++) acc[mt][nt][j] = 0.f;

    gemm_mainloop(g_Xh, g_Xl, g_Wqh, g_Wql, sm, m0, n0, acc);

    const int s = n0 >> 10;
    const int h = (n0 & 1023) >> 6;
    float* et = (float*)sm;

    __syncthreads();
#pragma unroll
    for (int mt = 0; mt < 2; mt++)
#pragma unroll
        for (int nt = 0; nt < 4; nt++) {
            int r0 = warp_m*32 + mt*16 + group;
            int col = warp_n*32 + nt*8 + 2*tg;
            *(float2*)&et[r0*66 + col] =
                make_float2(acc[mt][nt][0], acc[mt][nt][1]);
            *(float2*)&et[(r0+8)*66 + col] =
                make_float2(acc[mt][nt][2], acc[mt][nt][3]);
        }
    __syncthreads();
#pragma unroll
    for (int rr = 0; rr < 16; rr++) {
        int r  = warp*16 + rr;
        int gm = m0 + r;
        int bb = gm >> 11, n = gm & 2047;
        float v1 = et[r*66 + lane];
        float v2 = et[r*66 + lane + 32];
        size_t wbase = (((size_t)(bb*NHEADS + h))*SEQ + n)*32;
        if (s == 2) {
            pack_store_pair(g_vh, g_vl, wbase, lane, v1, v2);
        } else {
            float sum = v1 + v2, sq = v1*v1 + v2*v2;
#pragma unroll
            for (int o = 16; o; o >>= 1) {
                sum += __shfl_xor_sync(0xffffffffu, sum, o);
                sq  += __shfl_xor_sync(0xffffffffu, sq,  o);
            }
            float mean = sum * (1.f/64.f);
            float var  = sq  * (1.f/64.f) - mean*mean;
            float rstd = rsqrtf(var + 1e-5f);
            if (s == 0) {
                float y1 = ((v1-mean)*rstd*qw[lane]    + qb[lane])    * QSCALE;
                float y2 = ((v2-mean)*rstd*qw[lane+32] + qb[lane+32]) * QSCALE;
                pack_store_pair(g_qh, g_ql, wbase, lane, y1, y2);
            } else {
                float y1 = (v1-mean)*rstd*kw[lane]    + kb[lane];
                float y2 = (v2-mean)*rstd*kw[lane+32] + kb[lane+32];
                pack_store_pair(g_kh, g_kl, wbase, lane, y1, y2);
            }
        }
    }
}

// ---------------- kernel 3: output projection + bias ------------------------
__global__ __launch_bounds__(128, 4) void proj_gemm_kernel(
    const float* __restrict__ bias, float* __restrict__ out)
{
    __shared__ __align__(16) unsigned sm[8192];
    const int tid = threadIdx.x;
    const int m0 = blockIdx.y * 64, n0 = blockIdx.x * 64;
    const int warp = tid >> 5, lane = tid & 31;
    const int warp_m = warp >> 1, warp_n = warp & 1;
    const int group = lane >> 2, tg = lane & 3;

    float acc[2][4][4];
#pragma unroll
    for (int mt = 0; mt < 2; mt++)
#pragma unroll
        for (int nt = 0; nt < 4; nt++)
#pragma unroll
            for (int j = 0; j < 4; j++) acc[mt][nt][j] = 0.f;

    gemm_mainloop(g_aoh, g_aol, g_Pwh, g_Pwl, sm, m0, n0, acc);

#pragma unroll
    for (int nt = 0; nt < 4; nt++) {
        int col = n0 + warp_n*32 + nt*8 + 2*tg;
        float b0 = bias[col], b1 = bias[col+1];
#pragma unroll
        for (int mt = 0; mt < 2; mt++) {
            int row = m0 + warp_m*32 + mt*16 + group;
            *(float2*)(out + (size_t)row*MDIM + col) =
                make_float2(acc[mt][nt][0] + b0, acc[mt][nt][1] + b1);
            *(float2*)(out + (size_t)(row+8)*MDIM + col) =
                make_float2(acc[mt][nt][2] + b0, acc[mt][nt][3] + b1);
        }
    }
}

// ---------------- kernel 2: flash attention (2 CTAs/SM, ballot-skip) --------
__global__ __launch_bounds__(256, 2) void flash_attn_mma_kernel()
{
    extern __shared__ __align__(16) unsigned fsm[];
    const int tid = threadIdx.x;
    const int warp = tid >> 5, lane = tid & 31;
    const int group = lane >> 2, tg = lane & 3;
    const int q0 = blockIdx.x * 128, h = blockIdx.y, b = blockIdx.z;
    const int bhrow = (b*NHEADS + h)*SEQ;
    unsigned smb = (unsigned)__cvta_generic_to_shared(fsm);
    const unsigned kvb0 = smb + 32768;

    // ---- stage Q tile (persistent: hi at +0, lo at +16KB) ----
#pragma unroll
    for (int u = 0; u < 8; u++) {
        int ci = tid + u*256;
        int hl = ci >> 10, wi = ci & 1023;
        int row = wi >> 3, c = wi & 7;
        const unsigned* src = (hl ? g_ql : g_qh) + (size_t)(bhrow + q0 + row)*32 + c*4;
        cp16(smb + hl*16384 + row*128 + ((c ^ (row&7))<<4), src);
    }
    cp_commit();

    auto stageKV = [&](int kt, int buf) {
        unsigned base = kvb0 + buf*32768;
#pragma unroll
        for (int u = 0; u < 8; u++) {
            int ci = tid + u*256;
            int arr = ci >> 9, wi = ci & 511;
            int row = wi >> 3, c = wi & 7;
            const unsigned* sa;
            if (arr == 0) sa = g_kh; else if (arr == 1) sa = g_kl;
            else if (arr == 2) sa = g_vh; else sa = g_vl;
            const unsigned* src = sa + (size_t)(bhrow + kt*64 + row)*32 + c*4;
            cp16(base + arr*8192 + row*128 + ((c ^ (row&7))<<4), src);
        }
    };

    stageKV(0, 0); cp_commit();

    float m0r = MINIT, m1r = MINIT, l0r = 0.f, l1r = 0.f;
    float o[8][4];
#pragma unroll
    for (int nt = 0; nt < 8; nt++)
#pragma unroll
        for (int j = 0; j < 4; j++) o[nt][j] = 0.f;

    const int lr = warp*16 + group;
    const unsigned* mb0 = g_mb + (size_t)(b*SEQ + q0 + lr)*64;
    const unsigned* mb1 = g_mb + (size_t)(b*SEQ + q0 + lr + 8)*64;

    for (int kt = 0; kt < SEQ/64; kt++) {
        unsigned w0lo = mb0[kt*2], w0hi = mb0[kt*2+1];
        unsigned w1lo = mb1[kt*2], w1hi = mb1[kt*2+1];
        cp_wait<0>();
        __syncthreads();
        if (kt + 1 < SEQ/64) { stageKV(kt+1, (kt+1)&1); cp_commit(); }

        unsigned kb = kvb0 + (kt&1)*32768;

        // ---- S = Q K^T (bf16x3); Q frags re-loaded from smem per ks ----
        float s[8][4];
#pragma unroll
        for (int nt = 0; nt < 8; nt++)
#pragma unroll
            for (int j = 0; j < 4; j++) s[nt][j] = 0.f;
#pragma unroll
        for (int ks = 0; ks < 4; ks++) {
            unsigned qhf[4], qlf[4];
            {
                int row = warp*16 + (lane & 15);
                int ch = 2*ks + (lane >> 4);
                unsigned a = row*128 + ((ch ^ (row&7))<<4);
                ldsm4(smb + a,         qhf[0], qhf[1], qhf[2], qhf[3]);
                ldsm4(smb + 16384 + a, qlf[0], qlf[1], qlf[2], qlf[3]);
            }
#pragma unroll
            for (int ntp = 0; ntp < 4; ntp++) {
                int row = ntp*16 + (lane & 7) + ((lane & 16) >> 1);
                int ch = 2*ks + ((lane >> 3) & 1);
                unsigned a = kb + row*128 + ((ch ^ (row&7))<<4);
                unsigned bh0[2], bh1[2], bl0[2], bl1[2];
                ldsm4(a,        bh0[0], bh0[1], bh1[0], bh1[1]);
                ldsm4(a + 8192, bl0[0], bl0[1], bl1[0], bl1[1]);
                mma_bf16(s[2*ntp],   qhf, bh0);
                mma_bf16(s[2*ntp],   qhf, bl0);
                mma_bf16(s[2*ntp],   qlf, bh0);
                mma_bf16(s[2*ntp+1], qhf, bh1);
                mma_bf16(s[2*ntp+1], qhf, bl1);
                mma_bf16(s[2*ntp+1], qlf, bh1);
            }
        }

        // ---- mask + online softmax (base-2) ----
        float rm0 = MINIT, rm1 = MINIT;
#pragma unroll
        for (int nt = 0; nt < 8; nt++) {
            int kidx = nt*8 + 2*tg;
            unsigned wr0 = (nt < 4) ? w0lo : w0hi;
            unsigned wr1 = (nt < 4) ? w1lo : w1hi;
            int sh = kidx & 31;
            if ((wr0 >> sh) & 1)     s[nt][0] = MASKED;
            if ((wr0 >> (sh+1)) & 1) s[nt][1] = MASKED;
            if ((wr1 >> sh) & 1)     s[nt][2] = MASKED;
            if ((wr1 >> (sh+1)) & 1) s[nt][3] = MASKED;
            rm0 = fmaxf(rm0, fmaxf(s[nt][0], s[nt][1]));
            rm1 = fmaxf(rm1, fmaxf(s[nt][2], s[nt][3]));
        }
        rm0 = fmaxf(rm0, __shfl_xor_sync(0xffffffffu, rm0, 1));
        rm0 = fmaxf(rm0, __shfl_xor_sync(0xffffffffu, rm0, 2));
        rm1 = fmaxf(rm1, __shfl_xor_sync(0xffffffffu, rm1, 1));
        rm1 = fmaxf(rm1, __shfl_xor_sync(0xffffffffu, rm1, 2));
        float mn0 = fmaxf(m0r, rm0), mn1 = fmaxf(m1r, rm1);

        // ballot-guarded rescale: skipped ops are exactly *1.0 -> bit-identical
        bool nochg = (mn0 == m0r) && (mn1 == m1r);
        if (__ballot_sync(0xffffffffu, nochg) != 0xffffffffu) {
            float c0 = exp2f(m0r - mn0), c1 = exp2f(m1r - mn1);
            l0r *= c0; l1r *= c1;
#pragma unroll
            for (int nt = 0; nt < 8; nt++) {
                o[nt][0] *= c0; o[nt][1] *= c0;
                o[nt][2] *= c1; o[nt][3] *= c1;
            }
        }
        m0r = mn0; m1r = mn1;

        float ls0 = 0.f, ls1 = 0.f;
#pragma unroll
        for (int nt = 0; nt < 8; nt++) {
            s[nt][0] = exp2f(s[nt][0] - mn0);
            s[nt][1] = exp2f(s[nt][1] - mn0);
            s[nt][2] = exp2f(s[nt][2] - mn1);
            s[nt][3] = exp2f(s[nt][3] - mn1);
            ls0 += s[nt][0] + s[nt][1];
            ls1 += s[nt][2] + s[nt][3];
        }
        ls0 += __shfl_xor_sync(0xffffffffu, ls0, 1);
        ls0 += __shfl_xor_sync(0xffffffffu, ls0, 2);
        ls1 += __shfl_xor_sync(0xffffffffu, ls1, 1);
        ls1 += __shfl_xor_sync(0xffffffffu, ls1, 2);
        l0r += ls0;
        l1r += ls1;

        // ---- P fragments from S accumulators ----
        unsigned ph[4][4], pl[4][4];
#pragma unroll
        for (int j = 0; j < 4; j++) {
            cvt_pack(s[2*j][0],   s[2*j][1],   ph[j][0], pl[j][0]);
            cvt_pack(s[2*j][2],   s[2*j][3],   ph[j][1], pl[j][1]);
            cvt_pack(s[2*j+1][0], s[2*j+1][1], ph[j][2], pl[j][2]);
            cvt_pack(s[2*j+1][2], s[2*j+1][3], ph[j][3], pl[j][3]);
        }

        // ---- O += P V (V via ldmatrix.trans) ----
        unsigned vb = kb + 16384;
#pragma unroll
        for (int nt = 0; nt < 8; nt++) {
#pragma unroll
            for (int jp = 0; jp < 2; jp++) {
                int row = jp*32 + lane;
                unsigned a = vb + row*128 + ((nt ^ (row&7))<<4);
                unsigned vh0[2], vh1[2], vl0[2], vl1[2];
                ldsm4t(a,        vh0[0], vh0[1], vh1[0], vh1[1]);
                ldsm4t(a + 8192, vl0[0], vl0[1], vl1[0], vl1[1]);
                mma_bf16(o[nt], ph[2*jp],   vh0);
                mma_bf16(o[nt], ph[2*jp],   vl0);
                mma_bf16(o[nt], pl[2*jp],   vh0);
                mma_bf16(o[nt], ph[2*jp+1], vh1);
                mma_bf16(o[nt], ph[2*jp+1], vl1);
                mma_bf16(o[nt], pl[2*jp+1], vh1);
            }
        }
    }

    // ---- finalize: pack to bf16 hi/lo ao ----
    const int row0 = q0 + warp*16 + group;
    float inv0 = 1.f / l0r, inv1 = 1.f / l1r;
#pragma unroll
    for (int nt = 0; nt < 8; nt++) {
        int widx = h*32 + nt*4 + tg;
        unsigned hh, ll;
        cvt_pack(o[nt][0]*inv0, o[nt][1]*inv0, hh, ll);
        g_aoh[(size_t)(b*SEQ + row0)*512 + widx] = hh;
        g_aol[(size_t)(b*SEQ + row0)*512 + widx] = ll;
        cvt_pack(o[nt][2]*inv1, o[nt][3]*inv1, hh, ll);
        g_aoh[(size_t)(b*SEQ + row0 + 8)*512 + widx] = hh;
        g_aol[(size_t)(b*SEQ + row0 + 8)*512 + widx] = ll;
    }
}

// ---------------- launch ----------------------------------------------------
#define FLASH_SMEM (32768 + 2*32768)
#define PREP_GRID ((NW_ALL + NMASKW + 255)/256)

extern "C" void kernel_launch(void* const* d_in, const int* in_sizes, int n_in,
                              void* d_out, int out_size)
{
    const float* x      = (const float*)d_in[0];
    const void*  mask   = d_in[1];
    const float* qkv_w  = (const float*)d_in[2];
    const float* q_nw   = (const float*)d_in[3];
    const float* q_nb   = (const float*)d_in[4];
    const float* k_nw   = (const float*)d_in[5];
    const float* k_nb   = (const float*)d_in[6];
    const float* proj_w = (const float*)d_in[7];
    const float* proj_b = (const float*)d_in[8];
    float* out = (float*)d_out;

    probe_mask_kernel<<<1, 256>>>((const unsigned int*)mask);
    prep_all_kernel<<<PREP_GRID, 256>>>(x, qkv_w, proj_w, mask);

    qkv_gemm_ln_kernel<<<dim3(48, 64), 128>>>(q_nw, q_nb, k_nw, k_nb);

    cudaFuncSetAttribute(flash_attn_mma_kernel,
                         cudaFuncAttributeMaxDynamicSharedMemorySize, FLASH_SMEM);
    flash_attn_mma_kernel<<<dim3(16, NHEADS, BATCH), 256, FLASH_SMEM>>>();

    proj_gemm_kernel<<<dim3(16, 64), 128>>>(proj_b, out);
}